// round 13
// baseline (speedup 1.0000x reference)
#include <cuda_runtime.h>
#include <cstdint>

#define NN 50000
#define NE 800000
#define C  96
#define TM 128
#define NTILES 391            // ceil(NN/TM)
#define NPAIRS 196            // ceil(NTILES/2)
#define NB 148                // persistent blocks (co-resident, 1/SM)
#define NT 512
#define GSZ (NB * NT)
#define CHUNK 338             // ceil(NN/NB)

// ---------------- scratch (device globals; no allocation allowed) ----------
__device__ float g_H[NN * C];
__device__ float g_P[NN * C];
__device__ int   g_cnt[NN];
__device__ int   g_cursor[NN];
__device__ int   g_rowptr[NN + 1];
__device__ int2  g_edge[NE];          // (src, bits(w)) grouped by dst
__device__ int   g_bsum[NB];
__device__ unsigned g_bar_count;
__device__ unsigned g_bar_gen;

// ---------------- software grid barrier (all NB blocks co-resident) --------
__device__ __forceinline__ void grid_barrier() {
    __syncthreads();
    if (threadIdx.x == 0) {
        unsigned gen = *(volatile unsigned*)&g_bar_gen;
        __threadfence();
        if (atomicAdd(&g_bar_count, 1u) == NB - 1) {
            g_bar_count = 0u;
            __threadfence();
            *(volatile unsigned*)&g_bar_gen = gen + 1u;
        } else {
            while (*(volatile unsigned*)&g_bar_gen == gen) __nanosleep(64);
        }
    }
    __syncthreads();
}

// ---------------- GEMM tile (256 threads per tile, packed f32x2 math) ------
// ltid: ng = ltid>>3 (4 nodes), cg = ltid&7 (12 channels = 6 f32x2 pairs).
// Register-prefetched W/X chunks. Ws shared between halves; Xs per-half.
__device__ __forceinline__ void gemm_tile(const float* __restrict__ in,
                                          const float* __restrict__ W,
                                          float* __restrict__ out,
                                          int cin, int tile,
                                          float (*Xs)[33], float (*Ws)[96]) {
    const int tid = threadIdx.x;        // 0..511
    const int ltid = tid & 255;
    const int cg = ltid & 7;
    const int ng = ltid >> 3;
    const int node0 = tile * TM;

    int xr[4], xkq[4];
    const float* xbase[4];
#pragma unroll
    for (int i = 0; i < 4; i++) {
        int li = ltid + i * 256;
        xr[i] = li >> 3; xkq[i] = li & 7;
        int nd = node0 + xr[i];
        xbase[i] = (nd < NN) ? in + (size_t)nd * cin : nullptr;
    }
    int wr[3], wcq[3];
#pragma unroll
    for (int i = 0; i < 3; i++) {
        int li = tid + i * 256;
        wr[i] = li / 24; wcq[i] = li % 24;
    }

    unsigned long long acc2[4][6];
#pragma unroll
    for (int i = 0; i < 4; i++)
#pragma unroll
        for (int j = 0; j < 6; j++) acc2[i][j] = 0ull;

    const int nkc = cin >> 5;

    float4 px[4], pw[3];
#pragma unroll
    for (int i = 0; i < 4; i++)
        px[i] = xbase[i] ? __ldcg((const float4*)(xbase[i]) + xkq[i])
                         : make_float4(0.f, 0.f, 0.f, 0.f);
    if (tid < 256) {
#pragma unroll
        for (int i = 0; i < 3; i++)
            pw[i] = ((const float4*)(W + (size_t)wr[i] * 96))[wcq[i]];
    }

    for (int kc = 0; kc < nkc; kc++) {
        if (tid < 256) {
#pragma unroll
            for (int i = 0; i < 3; i++)
                *(float4*)&Ws[wr[i]][wcq[i] * 4] = pw[i];
        }
#pragma unroll
        for (int i = 0; i < 4; i++) {
            Xs[xr[i]][xkq[i] * 4 + 0] = px[i].x;
            Xs[xr[i]][xkq[i] * 4 + 1] = px[i].y;
            Xs[xr[i]][xkq[i] * 4 + 2] = px[i].z;
            Xs[xr[i]][xkq[i] * 4 + 3] = px[i].w;
        }
        __syncthreads();

        if (kc + 1 < nkc) {
            const int koff = (kc + 1) * 32;
#pragma unroll
            for (int i = 0; i < 4; i++)
                px[i] = xbase[i] ? __ldcg((const float4*)(xbase[i] + koff) + xkq[i])
                                 : make_float4(0.f, 0.f, 0.f, 0.f);
            if (tid < 256) {
#pragma unroll
                for (int i = 0; i < 3; i++)
                    pw[i] = ((const float4*)(W + (size_t)(koff + wr[i]) * 96))[wcq[i]];
            }
        }

#pragma unroll
        for (int k = 0; k < 32; k++) {
            const unsigned long long* wp =
                (const unsigned long long*)&Ws[k][cg * 12];
            unsigned long long w[6];
#pragma unroll
            for (int j = 0; j < 6; j++) w[j] = wp[j];
#pragma unroll
            for (int i = 0; i < 4; i++) {
                unsigned xb = __float_as_uint(Xs[ng * 4 + i][k]);
                unsigned long long xx;
                asm("mov.b64 %0, {%1, %1};" : "=l"(xx) : "r"(xb));
#pragma unroll
                for (int j = 0; j < 6; j++)
                    asm("fma.rn.f32x2 %0, %1, %2, %0;"
                        : "+l"(acc2[i][j]) : "l"(xx), "l"(w[j]));
            }
        }
        __syncthreads();
    }

#pragma unroll
    for (int i = 0; i < 4; i++) {
        int nd = node0 + ng * 4 + i;
        if (nd < NN) {
            unsigned long long* o =
                (unsigned long long*)(out + (size_t)nd * 96 + cg * 12);
#pragma unroll
            for (int j = 0; j < 6; j++) o[j] = acc2[i][j];
        }
    }
}

// ---------------- gather: warp/node, edge-batch software pipeline -----------
// Batch i+1's edge records are loaded BEFORE batch i's row loads are issued,
// so each 8-edge batch exposes ~one L2 latency instead of two.
__device__ __forceinline__ void gather_phase(const float* __restrict__ h,
                                             const float* __restrict__ b,
                                             float* __restrict__ out, int relu) {
    const int lane = threadIdx.x & 31;
    const int warp = threadIdx.x >> 5;
    const int gw = blockIdx.x * 16 + warp;    // 2368 warps total
    const float4* __restrict__ h4 = (const float4*)h;

    for (int node = gw; node < NN; node += NB * 16) {
        if (lane < 24) {
            const int beg = __ldcg(&g_rowptr[node]);
            const int end = __ldcg(&g_rowptr[node + 1]);

            float4 acc = make_float4(0.f, 0.f, 0.f, 0.f);
            float4 acc2 = make_float4(0.f, 0.f, 0.f, 0.f);
            int e = beg;
            bool have = (e + 8 <= end);
            int2 E[8];
            if (have) {
#pragma unroll
                for (int j = 0; j < 8; j++) E[j] = __ldcg(&g_edge[e + j]);
            }
            while (have) {
                const int en = e + 8;
                const bool haveN = (en + 8 <= end);
                int2 En[8];
                if (haveN) {
#pragma unroll
                    for (int j = 0; j < 8; j++) En[j] = __ldcg(&g_edge[en + j]);
                }
                float4 v[8];
#pragma unroll
                for (int j = 0; j < 8; j++)
                    v[j] = __ldcg(h4 + (size_t)E[j].x * 24 + lane);
#pragma unroll
                for (int j = 0; j < 4; j++) {
                    float w = __int_as_float(E[j].y);
                    acc.x += v[j].x * w; acc.y += v[j].y * w;
                    acc.z += v[j].z * w; acc.w += v[j].w * w;
                }
#pragma unroll
                for (int j = 4; j < 8; j++) {
                    float w = __int_as_float(E[j].y);
                    acc2.x += v[j].x * w; acc2.y += v[j].y * w;
                    acc2.z += v[j].z * w; acc2.w += v[j].w * w;
                }
#pragma unroll
                for (int j = 0; j < 8; j++) E[j] = En[j];
                e = en; have = haveN;
            }
            for (; e < end; e++) {
                int2 Et = __ldcg(&g_edge[e]);
                float4 v = __ldcg(h4 + (size_t)Et.x * 24 + lane);
                float w = __int_as_float(Et.y);
                acc.x += v.x * w; acc.y += v.y * w; acc.z += v.z * w; acc.w += v.w * w;
            }
            acc.x += acc2.x; acc.y += acc2.y; acc.z += acc2.z; acc.w += acc2.w;

            const float dii = 1.0f / (float)(__ldcg(&g_cnt[node]) + 1);  // dis^2 exact
            float4 hv = __ldcg(h4 + (size_t)node * 24 + lane);
            float4 bv = ((const float4*)b)[lane];
            acc.x += hv.x * dii + bv.x;
            acc.y += hv.y * dii + bv.y;
            acc.z += hv.z * dii + bv.z;
            acc.w += hv.w * dii + bv.w;
            if (relu) {
                acc.x = fmaxf(acc.x, 0.f); acc.y = fmaxf(acc.y, 0.f);
                acc.z = fmaxf(acc.z, 0.f); acc.w = fmaxf(acc.w, 0.f);
            }
            ((float4*)out)[(size_t)node * 24 + lane] = acc;
        }
    }
}

// ---------------- the one persistent kernel --------------------------------
__global__ __launch_bounds__(NT, 1) void gcn_mega_kernel(
    const float* __restrict__ x, const int* __restrict__ ei,
    const float* __restrict__ W1, const float* __restrict__ b1,
    const float* __restrict__ W2, const float* __restrict__ b2,
    const float* __restrict__ W3, const float* __restrict__ b3,
    const float* __restrict__ W4, const float* __restrict__ b4,
    float* __restrict__ out)
{
    __shared__ float Xs[2][TM][33];     // per-half X tiles
    __shared__ float Ws[32][96];        // shared W chunk
    int* sc = (int*)Ws;                 // scan scratch (NT ints)

    const int tid = threadIdx.x;
    const int gtid = blockIdx.x * NT + tid;

    // P0: zero cnt + cursor
    for (int i = gtid; i < NN; i += GSZ) { g_cnt[i] = 0; g_cursor[i] = 0; }
    grid_barrier();

    // P1: degree count
    for (int e = gtid; e < NE; e += GSZ) atomicAdd(&g_cnt[ei[NE + e]], 1);
    grid_barrier();

    // P2a: per-thread element + block exclusive scan (CHUNK=338 <= NT)
    const int base = blockIdx.x * CHUNK;
    const int lim = min(base + CHUNK, NN);
    const int myi = base + tid;
    int mysum = (myi < lim) ? __ldcg(&g_cnt[myi]) : 0;
    sc[tid] = mysum;
    __syncthreads();
    for (int off = 1; off < NT; off <<= 1) {
        int v = (tid >= off) ? sc[tid - off] : 0;
        __syncthreads();
        sc[tid] += v;
        __syncthreads();
    }
    int myexcl = sc[tid] - mysum;
    if (tid == NT - 1) g_bsum[blockIdx.x] = sc[tid];
    grid_barrier();

    // P2b: warp-parallel exclusive scan of NB block sums (block 0, warp 0)
    if (blockIdx.x == 0 && tid < 32) {
        int carry = 0;
        for (int b0 = 0; b0 < NB; b0 += 32) {
            int i = b0 + tid;
            int v = (i < NB) ? __ldcg(&g_bsum[i]) : 0;
            int orig = v;
#pragma unroll
            for (int o = 1; o < 32; o <<= 1) {
                int t = __shfl_up_sync(0xffffffffu, v, o);
                if ((tid & 31) >= o) v += t;
            }
            if (i < NB) g_bsum[i] = carry + v - orig;   // exclusive
            carry += __shfl_sync(0xffffffffu, v, 31);
        }
        if (tid == 0) g_rowptr[NN] = carry;
    }
    grid_barrier();

    // P2c: final rowptr
    if (myi < lim) g_rowptr[myi] = __ldcg(&g_bsum[blockIdx.x]) + myexcl;
    grid_barrier();

    // P3: fill CSR with precomputed edge weight
    for (int e = gtid; e < NE; e += GSZ) {
        int s = ei[e];
        int d = ei[NE + e];
        float w = rsqrtf((float)((__ldcg(&g_cnt[s]) + 1) * (__ldcg(&g_cnt[d]) + 1)));
        int pos = atomicAdd(&g_cursor[d], 1);
        g_edge[__ldcg(&g_rowptr[d]) + pos] = make_int2(s, __float_as_int(w));
    }
    grid_barrier();

    // layers
    const float* gin[4] = { x, g_P, g_P, g_P };
    const float* gW[4]  = { W1, W2, W3, W4 };
    const float* gb[4]  = { b1, b2, b3, b4 };
    float*       gout[4] = { g_P, g_P, g_P, out };
    const int    gcin[4] = { 128, 96, 96, 96 };

    const int half = tid >> 8;          // 0 or 1
    for (int l = 0; l < 4; l++) {
        for (int p = blockIdx.x; p < NPAIRS; p += NB) {
            int tile = 2 * p + half;
            if (tile >= NTILES) tile = NTILES - 1;   // tail: duplicate write, benign
            gemm_tile(gin[l], gW[l], g_H, gcin[l], tile, Xs[half], Ws);
        }
        grid_barrier();
        gather_phase(g_H, gb[l], gout[l], (l < 3) ? 1 : 0);
        if (l < 3) grid_barrier();
    }
}

// ---------------- launch ----------------------------------------------------
extern "C" void kernel_launch(void* const* d_in, const int* in_sizes, int n_in,
                              void* d_out, int out_size) {
    const float* x  = (const float*)d_in[0];
    const int*   ei = (const int*)d_in[1];   // int32 (JAX demotes int64)
    const float* W1 = (const float*)d_in[2];
    const float* b1 = (const float*)d_in[3];
    const float* W2 = (const float*)d_in[4];
    const float* b2 = (const float*)d_in[5];
    const float* W3 = (const float*)d_in[6];
    const float* b3 = (const float*)d_in[7];
    const float* W4 = (const float*)d_in[8];
    const float* b4 = (const float*)d_in[9];
    float* out = (float*)d_out;

    gcn_mega_kernel<<<NB, NT>>>(x, ei, W1, b1, W2, b2, W3, b3, W4, b4, out);
}

// round 15
// speedup vs baseline: 1.1457x; 1.1457x over previous
#include <cuda_runtime.h>
#include <cstdint>

#define NN 50000
#define NE 800000
#define C  96
#define TM 384                // nodes per block-wide GEMM tile
#define KC 16                 // k-chunk
#define WPAD 100              // Ws row stride in floats (400B: 16B-aligned rows)
#define NTILES 131            // ceil(NN/TM)
#define NB 148                // persistent blocks (co-resident, 1/SM)
#define NT 768
#define GSZ (NB * NT)
#define CHUNK 338             // ceil(NN/NB)

// ---------------- scratch (device globals; no allocation allowed) ----------
__device__ float g_H[NN * C];
__device__ float g_P[NN * C];
__device__ int   g_cnt[NN];
__device__ int   g_cursor[NN];
__device__ int   g_rowptr[NN + 1];
__device__ int2  g_edge[NE];          // (src, bits(w)) grouped by dst
__device__ int   g_bsum[NB];
__device__ unsigned g_bar_count;
__device__ unsigned g_bar_gen;

// ---------------- software grid barrier (all NB blocks co-resident) --------
__device__ __forceinline__ void grid_barrier() {
    __syncthreads();
    if (threadIdx.x == 0) {
        unsigned gen = *(volatile unsigned*)&g_bar_gen;
        __threadfence();
        if (atomicAdd(&g_bar_count, 1u) == NB - 1) {
            g_bar_count = 0u;
            __threadfence();
            *(volatile unsigned*)&g_bar_gen = gen + 1u;
        } else {
            while (*(volatile unsigned*)&g_bar_gen == gen) __nanosleep(64);
        }
    }
    __syncthreads();
}

// ---------------- GEMM tile: 768 threads, 384 nodes x 96 ch ----------------
// thread: cg = tid&7 (12 ch = 6 f32x2 pairs), ng = tid>>3 (4 nodes).
// k-chunks of 16, register-prefetched (X: 2 float4/thr, W: 1 float4 for tid<384).
__device__ __forceinline__ void gemm_tile(const float* __restrict__ in,
                                          const float* __restrict__ W,
                                          float* __restrict__ out,
                                          int cin, int tile,
                                          float (*Xs)[KC + 1], float (*Ws)[WPAD]) {
    const int tid = threadIdx.x;        // 0..767
    const int cg = tid & 7;
    const int ng = tid >> 3;            // 0..95 -> nodes ng*4..ng*4+3
    const int node0 = tile * TM;

    // X geometry: chunk = 384 rows x 16 k = 1536 float4; 2 per thread
    int xr[2], xkq[2];
    const float* xbase[2];
#pragma unroll
    for (int i = 0; i < 2; i++) {
        int li = tid + i * 768;
        xr[i] = li >> 2; xkq[i] = li & 3;       // 4 float4 per row-chunk
        int nd = node0 + xr[i];
        xbase[i] = (nd < NN) ? in + (size_t)nd * cin : nullptr;
    }
    // W geometry: chunk = 16 rows x 24 float4 = 384 float4; tid<384 loads 1
    const int wr = (tid < 384) ? (tid / 24) : 0;
    const int wcq = (tid < 384) ? (tid % 24) : 0;

    unsigned long long acc2[4][6];
#pragma unroll
    for (int i = 0; i < 4; i++)
#pragma unroll
        for (int j = 0; j < 6; j++) acc2[i][j] = 0ull;

    const int nkc = cin >> 4;

    // prologue: prefetch chunk 0
    float4 px[2], pw;
#pragma unroll
    for (int i = 0; i < 2; i++)
        px[i] = xbase[i] ? __ldcg((const float4*)(xbase[i]) + xkq[i])
                         : make_float4(0.f, 0.f, 0.f, 0.f);
    if (tid < 384)
        pw = ((const float4*)(W + (size_t)wr * 96))[wcq];

    for (int kc = 0; kc < nkc; kc++) {
        // commit prefetched chunk kc to smem
        if (tid < 384)
            *(float4*)&Ws[wr][wcq * 4] = pw;
#pragma unroll
        for (int i = 0; i < 2; i++) {
            Xs[xr[i]][xkq[i] * 4 + 0] = px[i].x;
            Xs[xr[i]][xkq[i] * 4 + 1] = px[i].y;
            Xs[xr[i]][xkq[i] * 4 + 2] = px[i].z;
            Xs[xr[i]][xkq[i] * 4 + 3] = px[i].w;
        }
        __syncthreads();

        // prefetch chunk kc+1 (overlaps compute)
        if (kc + 1 < nkc) {
            const int koff = (kc + 1) * KC;
#pragma unroll
            for (int i = 0; i < 2; i++)
                px[i] = xbase[i] ? __ldcg((const float4*)(xbase[i] + koff) + xkq[i])
                                 : make_float4(0.f, 0.f, 0.f, 0.f);
            if (tid < 384)
                pw = ((const float4*)(W + (size_t)(koff + wr) * 96))[wcq];
        }

#pragma unroll
        for (int k = 0; k < KC; k++) {
            const unsigned long long* wp =
                (const unsigned long long*)&Ws[k][cg * 12];
            unsigned long long w[6];
#pragma unroll
            for (int j = 0; j < 6; j++) w[j] = wp[j];
#pragma unroll
            for (int i = 0; i < 4; i++) {
                unsigned xb = __float_as_uint(Xs[ng * 4 + i][k]);
                unsigned long long xx;
                asm("mov.b64 %0, {%1, %1};" : "=l"(xx) : "r"(xb));
#pragma unroll
                for (int j = 0; j < 6; j++)
                    asm("fma.rn.f32x2 %0, %1, %2, %0;"
                        : "+l"(acc2[i][j]) : "l"(xx), "l"(w[j]));
            }
        }
        __syncthreads();
    }

#pragma unroll
    for (int i = 0; i < 4; i++) {
        int nd = node0 + ng * 4 + i;
        if (nd < NN) {
            unsigned long long* o =
                (unsigned long long*)(out + (size_t)nd * 96 + cg * 12);
#pragma unroll
            for (int j = 0; j < 6; j++) o[j] = acc2[i][j];
        }
    }
}

// ---------------- gather phase: warp per node (R10-proven shape) ------------
__device__ __forceinline__ void gather_phase(const float* __restrict__ h,
                                             const float* __restrict__ b,
                                             float* __restrict__ out, int relu) {
    const int lane = threadIdx.x & 31;
    const int warp = threadIdx.x >> 5;
    const int gw = blockIdx.x * 24 + warp;    // 3552 warps total
    const float4* __restrict__ h4 = (const float4*)h;

    for (int node = gw; node < NN; node += NB * 24) {
        if (lane < 24) {
            const int beg = __ldcg(&g_rowptr[node]);
            const int end = __ldcg(&g_rowptr[node + 1]);

            float4 acc = make_float4(0.f, 0.f, 0.f, 0.f);
            float4 acc2 = make_float4(0.f, 0.f, 0.f, 0.f);
            int e = beg;
            for (; e + 8 <= end; e += 8) {
                int2 E[8];
#pragma unroll
                for (int j = 0; j < 8; j++) E[j] = __ldcg(&g_edge[e + j]);
                float4 v[8];
#pragma unroll
                for (int j = 0; j < 8; j++) v[j] = __ldcg(h4 + (size_t)E[j].x * 24 + lane);
#pragma unroll
                for (int j = 0; j < 4; j++) {
                    float w = __int_as_float(E[j].y);
                    acc.x += v[j].x * w; acc.y += v[j].y * w;
                    acc.z += v[j].z * w; acc.w += v[j].w * w;
                }
#pragma unroll
                for (int j = 4; j < 8; j++) {
                    float w = __int_as_float(E[j].y);
                    acc2.x += v[j].x * w; acc2.y += v[j].y * w;
                    acc2.z += v[j].z * w; acc2.w += v[j].w * w;
                }
            }
            for (; e + 4 <= end; e += 4) {
                int2 E[4];
#pragma unroll
                for (int j = 0; j < 4; j++) E[j] = __ldcg(&g_edge[e + j]);
                float4 v[4];
#pragma unroll
                for (int j = 0; j < 4; j++) v[j] = __ldcg(h4 + (size_t)E[j].x * 24 + lane);
#pragma unroll
                for (int j = 0; j < 4; j++) {
                    float w = __int_as_float(E[j].y);
                    acc.x += v[j].x * w; acc.y += v[j].y * w;
                    acc.z += v[j].z * w; acc.w += v[j].w * w;
                }
            }
            for (; e < end; e++) {
                int2 E = __ldcg(&g_edge[e]);
                float4 v = __ldcg(h4 + (size_t)E.x * 24 + lane);
                float w = __int_as_float(E.y);
                acc.x += v.x * w; acc.y += v.y * w; acc.z += v.z * w; acc.w += v.w * w;
            }
            acc.x += acc2.x; acc.y += acc2.y; acc.z += acc2.z; acc.w += acc2.w;

            const float dii = 1.0f / (float)(__ldcg(&g_cnt[node]) + 1);  // dis^2 exact
            float4 hv = __ldcg(h4 + (size_t)node * 24 + lane);
            float4 bv = ((const float4*)b)[lane];
            acc.x += hv.x * dii + bv.x;
            acc.y += hv.y * dii + bv.y;
            acc.z += hv.z * dii + bv.z;
            acc.w += hv.w * dii + bv.w;
            if (relu) {
                acc.x = fmaxf(acc.x, 0.f); acc.y = fmaxf(acc.y, 0.f);
                acc.z = fmaxf(acc.z, 0.f); acc.w = fmaxf(acc.w, 0.f);
            }
            ((float4*)out)[(size_t)node * 24 + lane] = acc;
        }
    }
}

// ---------------- the one persistent kernel --------------------------------
__global__ __launch_bounds__(NT, 1) void gcn_mega_kernel(
    const float* __restrict__ x, const int* __restrict__ ei,
    const float* __restrict__ W1, const float* __restrict__ b1,
    const float* __restrict__ W2, const float* __restrict__ b2,
    const float* __restrict__ W3, const float* __restrict__ b3,
    const float* __restrict__ W4, const float* __restrict__ b4,
    float* __restrict__ out)
{
    __shared__ float Xs[TM][KC + 1];    // 384 x 17 floats = 26.1 KB
    __shared__ float Ws[KC][WPAD];      // 16 x 100 floats = 6.4 KB (16B rows)
    int* sc = (int*)Xs;                 // scan scratch (NT ints = 3 KB)

    const int tid = threadIdx.x;
    const int gtid = blockIdx.x * NT + tid;

    // P0: zero cnt + cursor
    for (int i = gtid; i < NN; i += GSZ) { g_cnt[i] = 0; g_cursor[i] = 0; }
    grid_barrier();

    // P1: degree count
    for (int e = gtid; e < NE; e += GSZ) atomicAdd(&g_cnt[ei[NE + e]], 1);
    grid_barrier();

    // P2a: per-thread element + block exclusive scan (CHUNK=338 <= NT)
    const int base = blockIdx.x * CHUNK;
    const int lim = min(base + CHUNK, NN);
    const int myi = base + tid;
    int mysum = (myi < lim) ? __ldcg(&g_cnt[myi]) : 0;
    sc[tid] = mysum;
    __syncthreads();
    for (int off = 1; off < NT; off <<= 1) {
        int v = (tid >= off) ? sc[tid - off] : 0;
        __syncthreads();
        sc[tid] += v;
        __syncthreads();
    }
    int myexcl = sc[tid] - mysum;
    if (tid == NT - 1) g_bsum[blockIdx.x] = sc[tid];
    grid_barrier();

    // P2b: warp-parallel exclusive scan of NB block sums (block 0, warp 0)
    if (blockIdx.x == 0 && tid < 32) {
        int carry = 0;
        for (int b0 = 0; b0 < NB; b0 += 32) {
            int i = b0 + tid;
            int v = (i < NB) ? __ldcg(&g_bsum[i]) : 0;
            int orig = v;
#pragma unroll
            for (int o = 1; o < 32; o <<= 1) {
                int t = __shfl_up_sync(0xffffffffu, v, o);
                if ((tid & 31) >= o) v += t;
            }
            if (i < NB) g_bsum[i] = carry + v - orig;   // exclusive
            carry += __shfl_sync(0xffffffffu, v, 31);
        }
        if (tid == 0) g_rowptr[NN] = carry;
    }
    grid_barrier();

    // P2c: final rowptr
    if (myi < lim) g_rowptr[myi] = __ldcg(&g_bsum[blockIdx.x]) + myexcl;
    grid_barrier();

    // P3: fill CSR with precomputed edge weight
    for (int e = gtid; e < NE; e += GSZ) {
        int s = ei[e];
        int d = ei[NE + e];
        float w = rsqrtf((float)((__ldcg(&g_cnt[s]) + 1) * (__ldcg(&g_cnt[d]) + 1)));
        int pos = atomicAdd(&g_cursor[d], 1);
        g_edge[__ldcg(&g_rowptr[d]) + pos] = make_int2(s, __float_as_int(w));
    }
    grid_barrier();

    // layers: one 384-node tile per block per layer (131 tiles <= 148 blocks)
    const float* gin[4] = { x, g_P, g_P, g_P };
    const float* gW[4]  = { W1, W2, W3, W4 };
    const float* gb[4]  = { b1, b2, b3, b4 };
    float*       gout[4] = { g_P, g_P, g_P, out };
    const int    gcin[4] = { 128, 96, 96, 96 };

    for (int l = 0; l < 4; l++) {
        if (blockIdx.x < NTILES)
            gemm_tile(gin[l], gW[l], g_H, gcin[l], blockIdx.x, Xs, Ws);
        grid_barrier();
        gather_phase(g_H, gb[l], gout[l], (l < 3) ? 1 : 0);
        if (l < 3) grid_barrier();
    }
}

// ---------------- launch ----------------------------------------------------
extern "C" void kernel_launch(void* const* d_in, const int* in_sizes, int n_in,
                              void* d_out, int out_size) {
    const float* x  = (const float*)d_in[0];
    const int*   ei = (const int*)d_in[1];   // int32 (JAX demotes int64)
    const float* W1 = (const float*)d_in[2];
    const float* b1 = (const float*)d_in[3];
    const float* W2 = (const float*)d_in[4];
    const float* b2 = (const float*)d_in[5];
    const float* W3 = (const float*)d_in[6];
    const float* b3 = (const float*)d_in[7];
    const float* W4 = (const float*)d_in[8];
    const float* b4 = (const float*)d_in[9];
    float* out = (float*)d_out;

    gcn_mega_kernel<<<NB, NT>>>(x, ei, W1, b1, W2, b2, W3, b3, W4, b4, out);
}